// round 1
// baseline (speedup 1.0000x reference)
#include <cuda_runtime.h>

// LieTransport: bilinear backward warp.
// h_prev: [B=4, C=64, H=128, W=128, R=16] fp32
// flow:   [B, 2, H, W] fp32
// dt:     [B] fp32
// out:    same shape as h_prev
//
// One 256-thread block per output pixel (b,y,x).
// Thread t -> channel c = t/4, float4 quarter q = t%4 of the R=16 row.

#define Hd 128
#define Wd 128
#define Cd 64

__global__ __launch_bounds__(256, 8) void lie_transport_kernel(
    const float4* __restrict__ h4,
    const float*  __restrict__ flow,
    const float*  __restrict__ dt,
    float4*       __restrict__ out4)
{
    const int pix = blockIdx.x;
    const int x = pix & (Wd - 1);
    const int y = (pix >> 7) & (Hd - 1);
    const int b = pix >> 14;

    // --- sampling coordinates (uniform across the block; redundant compute) ---
    const float d  = dt[b];
    const int   fb = ((b * 2) * Hd + y) * Wd + x;
    const float fx = flow[fb];
    const float fy = flow[fb + Hd * Wd];

    // base grid: linspace(-1,1,N)[i] = -1 + 2*i/(N-1)
    const float gx = fmaf((float)x, 2.0f / (Wd - 1), -1.0f) - fx * d;
    const float gy = fmaf((float)y, 2.0f / (Hd - 1), -1.0f) - fy * d;

    float ix = fminf(fmaxf(((gx + 1.0f) * (float)Wd - 1.0f) * 0.5f, 0.0f), (float)(Wd - 1));
    float iy = fminf(fmaxf(((gy + 1.0f) * (float)Hd - 1.0f) * 0.5f, 0.0f), (float)(Hd - 1));

    const float x0f = floorf(ix);
    const float y0f = floorf(iy);
    const float wx  = ix - x0f;
    const float wy  = iy - y0f;

    const int x0 = (int)x0f;
    const int y0 = (int)y0f;
    const int x1 = min(x0 + 1, Wd - 1);
    const int y1 = min(y0 + 1, Hd - 1);

    // --- per-thread channel/quarter ---
    const int tid = threadIdx.x;
    const int c   = tid >> 2;
    const int q   = tid & 3;

    // float4 linear index: (((b*C + c)*H + yy)*W + xx)*4 + q
    const int cbase = (b * Cd + c) * (Hd * Wd * 4);

    const int i00 = cbase + (y0 * Wd + x0) * 4 + q;
    const int i01 = cbase + (y0 * Wd + x1) * 4 + q;
    const int i10 = cbase + (y1 * Wd + x0) * 4 + q;
    const int i11 = cbase + (y1 * Wd + x1) * 4 + q;

    const float4 v00 = h4[i00];
    const float4 v01 = h4[i01];
    const float4 v10 = h4[i10];
    const float4 v11 = h4[i11];

    float4 top, bot, r;
    top.x = fmaf(wx, v01.x - v00.x, v00.x);
    top.y = fmaf(wx, v01.y - v00.y, v00.y);
    top.z = fmaf(wx, v01.z - v00.z, v00.z);
    top.w = fmaf(wx, v01.w - v00.w, v00.w);

    bot.x = fmaf(wx, v11.x - v10.x, v10.x);
    bot.y = fmaf(wx, v11.y - v10.y, v10.y);
    bot.z = fmaf(wx, v11.z - v10.z, v10.z);
    bot.w = fmaf(wx, v11.w - v10.w, v10.w);

    r.x = fmaf(wy, bot.x - top.x, top.x);
    r.y = fmaf(wy, bot.y - top.y, top.y);
    r.z = fmaf(wy, bot.z - top.z, top.z);
    r.w = fmaf(wy, bot.w - top.w, top.w);

    out4[cbase + (y * Wd + x) * 4 + q] = r;
}

extern "C" void kernel_launch(void* const* d_in, const int* in_sizes, int n_in,
                              void* d_out, int out_size)
{
    const float* h_prev = (const float*)d_in[0];
    const float* flow   = (const float*)d_in[1];
    const float* dt     = (const float*)d_in[2];
    float* out          = (float*)d_out;

    const int B = 4;
    dim3 grid(B * Hd * Wd);   // 65536 blocks, one per output pixel
    dim3 block(256);          // C=64 channels x 4 float4 quarters

    lie_transport_kernel<<<grid, block>>>(
        (const float4*)h_prev, flow, dt, (float4*)out);
}